// round 2
// baseline (speedup 1.0000x reference)
#include <cuda_runtime.h>

// Problem constants
#define B_  256
#define S_  256
#define E_  256
#define H_  1024
#define G4  4096   // 4*H

// ---------------------------------------------------------------------------
// Device-global scratch (static arrays: no runtime allocation allowed)
// ---------------------------------------------------------------------------
// projL[l][c] = letter_emb[l] . W_ih[r(c), :E] + b_ih[r] + b_hh[r]
// projS[t][c] = state_emb[t]  . W_ih[r(c), E:2E]
// column reorder: c = 4*k + g  where r(c) = g*H + k  (gate order i,f,g,o)
__device__ float g_projL[30 * G4];
__device__ float g_projS[4 * G4];
// Reordered recurrent weights: Wt[kk][c] = W_hh[g*H + k][kk]  (16 MB, L2-resident)
__device__ float g_Wt[H_ * G4];
// Double-buffered hidden state, transposed: hT[k][b]  (1 MB each)
__device__ float g_hT[2][H_ * B_];
// Grid barrier counter
__device__ unsigned int g_bar;

// ---------------------------------------------------------------------------
// f32x2 packed-FMA helpers (sm_103a FFMA2 — only reachable via PTX)
// ---------------------------------------------------------------------------
__device__ __forceinline__ unsigned long long pack2(float x, float y) {
    unsigned long long r;
    asm("mov.b64 %0, {%1, %2};" : "=l"(r) : "f"(x), "f"(y));
    return r;
}
__device__ __forceinline__ void unpack2(float& lo, float& hi, unsigned long long v) {
    asm("mov.b64 {%0, %1}, %2;" : "=f"(lo), "=f"(hi) : "l"(v));
}
__device__ __forceinline__ void ffma2(unsigned long long& d,
                                      unsigned long long a,
                                      unsigned long long b) {
    asm("fma.rn.f32x2 %0, %1, %2, %0;" : "+l"(d) : "l"(a), "l"(b));
}

__device__ __forceinline__ float sigf(float x) {
    return __fdividef(1.0f, 1.0f + __expf(-x));
}
__device__ __forceinline__ float tanhfast(float x) {
    return __fdividef(2.0f, 1.0f + __expf(-2.0f * x)) - 1.0f;
}

// ---------------------------------------------------------------------------
// Prep kernels (run each launch; graph-replay deterministic)
// ---------------------------------------------------------------------------
__global__ void zero_kernel() {
    int idx = blockIdx.x * blockDim.x + threadIdx.x;
    if (idx < H_ * B_) g_hT[0][idx] = 0.0f;
    if (idx == 0) g_bar = 0u;
}

__global__ void proj_kernel(const float* __restrict__ letter_emb,
                            const float* __restrict__ state_emb,
                            const float* __restrict__ W_ih,
                            const float* __restrict__ b_ih,
                            const float* __restrict__ b_hh) {
    int idx = blockIdx.x * blockDim.x + threadIdx.x;
    if (idx >= 34 * G4) return;
    int tbl = idx >> 12;           // 0..33
    int c   = idx & (G4 - 1);
    int k = c >> 2, g = c & 3;
    int r = g * H_ + k;
    if (tbl < 30) {
        const float* e = letter_emb + tbl * E_;
        const float* w = W_ih + (size_t)r * (2 * E_);
        float sum = __ldg(b_ih + r) + __ldg(b_hh + r);
        for (int i = 0; i < E_; i++) sum += __ldg(e + i) * __ldg(w + i);
        g_projL[tbl * G4 + c] = sum;
    } else {
        const float* e = state_emb + (tbl - 30) * E_;
        const float* w = W_ih + (size_t)r * (2 * E_) + E_;
        float sum = 0.0f;
        for (int i = 0; i < E_; i++) sum += __ldg(e + i) * __ldg(w + i);
        g_projS[(tbl - 30) * G4 + c] = sum;
    }
}

__global__ void wt_kernel(const float* __restrict__ W_hh) {
    int idx = blockIdx.x * blockDim.x + threadIdx.x;   // over H_*G4
    int c  = idx & (G4 - 1);
    int kk = idx >> 12;
    int k = c >> 2, g = c & 3;
    g_Wt[idx] = __ldg(W_hh + (size_t)(g * H_ + k) * H_ + kk);
}

// ---------------------------------------------------------------------------
// Persistent recurrent kernel.
// grid = 128 CTAs: blockIdx = bt*64 + kt
//   bt in {0,1}: batch tile of 128
//   kt in [0,64): hidden-unit tile of 16 (-> 64 contiguous reordered gate cols)
// 256 threads = 16 (tr: batch sub-tiles of 8) x 16 (tc: one hidden unit each).
// Each thread owns 8 batch rows x 1 hidden unit: all 4 gates, c-state in regs.
// ---------------------------------------------------------------------------
__global__ void __launch_bounds__(256)
lstm_kernel(const int* __restrict__ letter_seq,
            const int* __restrict__ state_seq,
            float* __restrict__ out) {
    const int bt = blockIdx.x >> 6;
    const int kt = blockIdx.x & 63;
    const int b0 = bt * 128;
    const int c0 = kt * 64;
    const int t  = threadIdx.x;
    const int tr = t >> 4;          // 0..15
    const int tc = t & 15;          // 0..15
    const int myk   = kt * 16 + tc; // this thread's hidden unit
    const int bbase = tr * 8;       // batch offset within tile
    const unsigned grid = gridDim.x;

    __shared__ float hs[32][128];   // h chunk  [kk][b]
    __shared__ float ws[32][64];    // W chunk  [kk][c]

    float cst[8];
#pragma unroll
    for (int j = 0; j < 8; j++) cst[j] = 0.0f;

    for (int s = 0; s < S_; ++s) {
        const float* __restrict__ hTp = g_hT[s & 1];
        float* __restrict__ hTn = g_hT[(s + 1) & 1];

        unsigned long long acc[4][4];   // [batch-pair][gate], each = 2 batches
#pragma unroll
        for (int i = 0; i < 4; i++)
#pragma unroll
            for (int j = 0; j < 4; j++) acc[i][j] = 0ull;

        // ---- gates += h_prev @ W_hh^T (reordered cols) ----
        for (int kk0 = 0; kk0 < H_; kk0 += 32) {
#pragma unroll
            for (int i = 0; i < 4; i++) {
                int idx = t + 256 * i;            // 1024 float4 slots
                int row = idx >> 5;
                int col = (idx & 31) << 2;
                float4 v = __ldcg((const float4*)(hTp + (kk0 + row) * B_ + b0 + col));
                *(float4*)&hs[row][col] = v;
            }
#pragma unroll
            for (int i = 0; i < 2; i++) {
                int idx = t + 256 * i;            // 512 float4 slots
                int row = idx >> 4;
                int col = (idx & 15) << 2;
                float4 v = __ldg((const float4*)(g_Wt + (size_t)(kk0 + row) * G4 + c0 + col));
                *(float4*)&ws[row][col] = v;
            }
            __syncthreads();
#pragma unroll
            for (int kk = 0; kk < 32; ++kk) {
                float4 w = *(const float4*)&ws[kk][tc << 2];
                unsigned long long ww4[4];
                ww4[0] = pack2(w.x, w.x);
                ww4[1] = pack2(w.y, w.y);
                ww4[2] = pack2(w.z, w.z);
                ww4[3] = pack2(w.w, w.w);
                const unsigned long long* hp =
                    (const unsigned long long*)&hs[kk][bbase];
                unsigned long long hh4[4] = {hp[0], hp[1], hp[2], hp[3]};
#pragma unroll
                for (int bp = 0; bp < 4; bp++)
#pragma unroll
                    for (int cj = 0; cj < 4; cj++)
                        ffma2(acc[bp][cj], hh4[bp], ww4[cj]);
            }
            __syncthreads();
        }

        // ---- epilogue: + x_proj gather, activations, c/h update, stores ----
        float hvals[8];
#pragma unroll
        for (int bp = 0; bp < 4; ++bp) {
            float iv[2], fv[2], gv[2], ov[2];
            unpack2(iv[0], iv[1], acc[bp][0]);
            unpack2(fv[0], fv[1], acc[bp][1]);
            unpack2(gv[0], gv[1], acc[bp][2]);
            unpack2(ov[0], ov[1], acc[bp][3]);
#pragma unroll
            for (int ln = 0; ln < 2; ++ln) {
                int j = bp * 2 + ln;
                int b = b0 + bbase + j;
                int ltok = __ldg(letter_seq + b * S_ + s);
                int stok = __ldg(state_seq + b * S_ + s);
                float4 pl = __ldg((const float4*)(g_projL + ltok * G4 + c0 + (tc << 2)));
                float4 ps = __ldg((const float4*)(g_projS + stok * G4 + c0 + (tc << 2)));
                float xi = iv[ln] + pl.x + ps.x;
                float xf = fv[ln] + pl.y + ps.y;
                float xg = gv[ln] + pl.z + ps.z;
                float xo = ov[ln] + pl.w + ps.w;
                float I  = sigf(xi);
                float F  = sigf(xf);
                float O  = sigf(xo);
                float Gv = tanhfast(xg);
                float cc = F * cst[j] + I * Gv;
                cst[j] = cc;
                float hh = O * tanhfast(cc);
                hvals[j] = hh;
                int base = b * (S_ * H_) + s * H_ + myk;
                out[base] = hh;                       // hidden
                out[B_ * S_ * H_ + base] = cc;        // cell
            }
        }
        // publish h for next step (transposed layout, L2 via st.cg)
        float4 v0 = make_float4(hvals[0], hvals[1], hvals[2], hvals[3]);
        float4 v1 = make_float4(hvals[4], hvals[5], hvals[6], hvals[7]);
        __stcg((float4*)(hTn + myk * B_ + b0 + bbase), v0);
        __stcg((float4*)(hTn + myk * B_ + b0 + bbase + 4), v1);

        // ---- grid-wide barrier ----
        __syncthreads();
        if (t == 0) {
            __threadfence();
            atomicAdd(&g_bar, 1u);
            unsigned target = (unsigned)(s + 1) * grid;
            while (*((volatile unsigned*)&g_bar) < target) { }
        }
        __syncthreads();
    }
}

// ---------------------------------------------------------------------------
extern "C" void kernel_launch(void* const* d_in, const int* in_sizes, int n_in,
                              void* d_out, int out_size) {
    const int*   letter_seq = (const int*)d_in[0];
    const int*   state_seq  = (const int*)d_in[1];
    const float* letter_emb = (const float*)d_in[2];
    const float* state_emb  = (const float*)d_in[3];
    const float* W_ih       = (const float*)d_in[4];
    const float* W_hh       = (const float*)d_in[5];
    const float* b_ih       = (const float*)d_in[6];
    const float* b_hh       = (const float*)d_in[7];
    float* out = (float*)d_out;

    zero_kernel<<<(H_ * B_ + 255) / 256, 256>>>();
    proj_kernel<<<(34 * G4 + 255) / 256, 256>>>(letter_emb, state_emb, W_ih, b_ih, b_hh);
    wt_kernel<<<(H_ * G4) / 256, 256>>>(W_hh);
    lstm_kernel<<<128, 256>>>(letter_seq, state_seq, out);
}

// round 3
// speedup vs baseline: 1.0038x; 1.0038x over previous
#include <cuda_runtime.h>

// Problem constants
#define B_  256
#define S_  256
#define E_  256
#define H_  1024
#define G4  4096   // 4*H

// ---------------------------------------------------------------------------
// Device-global scratch (static arrays: no runtime allocation allowed)
// ---------------------------------------------------------------------------
// projL[l][c] = letter_emb[l] . W_ih[r(c), :E] + b_ih[r] + b_hh[r]
// projS[t][c] = state_emb[t]  . W_ih[r(c), E:2E]
// column reorder: c = 4*k + g  where r(c) = g*H + k  (gate order i,f,g,o)
__device__ float g_projL[30 * G4];
__device__ float g_projS[4 * G4];
// Reordered recurrent weights: Wt[kk][c] = W_hh[g*H + k][kk]  (16 MB, L2-resident)
__device__ float g_Wt[H_ * G4];
// Double-buffered hidden state, transposed: hT[k][b]  (1 MB each)
__device__ float g_hT[2][H_ * B_];
// Grid barrier counter
__device__ unsigned int g_bar;

// ---------------------------------------------------------------------------
// f32x2 packed-FMA helpers (sm_103a FFMA2 — only reachable via PTX)
// ---------------------------------------------------------------------------
__device__ __forceinline__ unsigned long long pack2(float x, float y) {
    unsigned long long r;
    asm("mov.b64 %0, {%1, %2};" : "=l"(r) : "f"(x), "f"(y));
    return r;
}
__device__ __forceinline__ void unpack2(float& lo, float& hi, unsigned long long v) {
    asm("mov.b64 {%0, %1}, %2;" : "=f"(lo), "=f"(hi) : "l"(v));
}
__device__ __forceinline__ void ffma2(unsigned long long& d,
                                      unsigned long long a,
                                      unsigned long long b) {
    asm("fma.rn.f32x2 %0, %1, %2, %0;" : "+l"(d) : "l"(a), "l"(b));
}

__device__ __forceinline__ float sigf(float x) {
    return __fdividef(1.0f, 1.0f + __expf(-x));
}
__device__ __forceinline__ float tanhfast(float x) {
    return __fdividef(2.0f, 1.0f + __expf(-2.0f * x)) - 1.0f;
}

// ---------------------------------------------------------------------------
// Prep kernels (run each launch; graph-replay deterministic)
// ---------------------------------------------------------------------------
__global__ void zero_kernel() {
    int idx = blockIdx.x * blockDim.x + threadIdx.x;
    if (idx < H_ * B_) g_hT[0][idx] = 0.0f;
    if (idx == 0) g_bar = 0u;
}

__global__ void proj_kernel(const float* __restrict__ letter_emb,
                            const float* __restrict__ state_emb,
                            const float* __restrict__ W_ih,
                            const float* __restrict__ b_ih,
                            const float* __restrict__ b_hh) {
    int idx = blockIdx.x * blockDim.x + threadIdx.x;
    if (idx >= 34 * G4) return;
    int tbl = idx >> 12;           // 0..33
    int c   = idx & (G4 - 1);
    int k = c >> 2, g = c & 3;
    int r = g * H_ + k;
    if (tbl < 30) {
        const float* e = letter_emb + tbl * E_;
        const float* w = W_ih + (size_t)r * (2 * E_);
        float sum = __ldg(b_ih + r) + __ldg(b_hh + r);
        for (int i = 0; i < E_; i++) sum += __ldg(e + i) * __ldg(w + i);
        g_projL[tbl * G4 + c] = sum;
    } else {
        const float* e = state_emb + (tbl - 30) * E_;
        const float* w = W_ih + (size_t)r * (2 * E_) + E_;
        float sum = 0.0f;
        for (int i = 0; i < E_; i++) sum += __ldg(e + i) * __ldg(w + i);
        g_projS[(tbl - 30) * G4 + c] = sum;
    }
}

__global__ void wt_kernel(const float* __restrict__ W_hh) {
    int idx = blockIdx.x * blockDim.x + threadIdx.x;   // over H_*G4
    int c  = idx & (G4 - 1);
    int kk = idx >> 12;
    int k = c >> 2, g = c & 3;
    g_Wt[idx] = __ldg(W_hh + (size_t)(g * H_ + k) * H_ + kk);
}

// ---------------------------------------------------------------------------
// Persistent recurrent kernel.
// grid = 128 CTAs: blockIdx = bt*64 + kt
//   bt in {0,1}: batch tile of 128
//   kt in [0,64): hidden-unit tile of 16 (-> 64 contiguous reordered gate cols)
// 256 threads = 16 (tr: batch sub-tiles of 8) x 16 (tc: one hidden unit each).
// Each thread owns 8 batch rows x 1 hidden unit: all 4 gates, c-state in regs.
// ---------------------------------------------------------------------------
__global__ void __launch_bounds__(256)
lstm_kernel(const int* __restrict__ letter_seq,
            const int* __restrict__ state_seq,
            float* __restrict__ out) {
    const int bt = blockIdx.x >> 6;
    const int kt = blockIdx.x & 63;
    const int b0 = bt * 128;
    const int c0 = kt * 64;
    const int t  = threadIdx.x;
    const int tr = t >> 4;          // 0..15
    const int tc = t & 15;          // 0..15
    const int myk   = kt * 16 + tc; // this thread's hidden unit
    const int bbase = tr * 8;       // batch offset within tile
    const unsigned grid = gridDim.x;

    __shared__ float hs[32][128];   // h chunk  [kk][b]
    __shared__ float ws[32][64];    // W chunk  [kk][c]

    float cst[8];
#pragma unroll
    for (int j = 0; j < 8; j++) cst[j] = 0.0f;

    for (int s = 0; s < S_; ++s) {
        const float* __restrict__ hTp = g_hT[s & 1];
        float* __restrict__ hTn = g_hT[(s + 1) & 1];

        unsigned long long acc[4][4];   // [batch-pair][gate], each = 2 batches
#pragma unroll
        for (int i = 0; i < 4; i++)
#pragma unroll
            for (int j = 0; j < 4; j++) acc[i][j] = 0ull;

        // ---- gates += h_prev @ W_hh^T (reordered cols) ----
        for (int kk0 = 0; kk0 < H_; kk0 += 32) {
#pragma unroll
            for (int i = 0; i < 4; i++) {
                int idx = t + 256 * i;            // 1024 float4 slots
                int row = idx >> 5;
                int col = (idx & 31) << 2;
                float4 v = __ldcg((const float4*)(hTp + (kk0 + row) * B_ + b0 + col));
                *(float4*)&hs[row][col] = v;
            }
#pragma unroll
            for (int i = 0; i < 2; i++) {
                int idx = t + 256 * i;            // 512 float4 slots
                int row = idx >> 4;
                int col = (idx & 15) << 2;
                float4 v = __ldg((const float4*)(g_Wt + (size_t)(kk0 + row) * G4 + c0 + col));
                *(float4*)&ws[row][col] = v;
            }
            __syncthreads();
#pragma unroll
            for (int kk = 0; kk < 32; ++kk) {
                float4 w = *(const float4*)&ws[kk][tc << 2];
                unsigned long long ww4[4];
                ww4[0] = pack2(w.x, w.x);
                ww4[1] = pack2(w.y, w.y);
                ww4[2] = pack2(w.z, w.z);
                ww4[3] = pack2(w.w, w.w);
                const unsigned long long* hp =
                    (const unsigned long long*)&hs[kk][bbase];
                unsigned long long hh4[4] = {hp[0], hp[1], hp[2], hp[3]};
#pragma unroll
                for (int bp = 0; bp < 4; bp++)
#pragma unroll
                    for (int cj = 0; cj < 4; cj++)
                        ffma2(acc[bp][cj], hh4[bp], ww4[cj]);
            }
            __syncthreads();
        }

        // ---- epilogue: + x_proj gather, activations, c/h update, stores ----
        float hvals[8];
#pragma unroll
        for (int bp = 0; bp < 4; ++bp) {
            float iv[2], fv[2], gv[2], ov[2];
            unpack2(iv[0], iv[1], acc[bp][0]);
            unpack2(fv[0], fv[1], acc[bp][1]);
            unpack2(gv[0], gv[1], acc[bp][2]);
            unpack2(ov[0], ov[1], acc[bp][3]);
#pragma unroll
            for (int ln = 0; ln < 2; ++ln) {
                int j = bp * 2 + ln;
                int b = b0 + bbase + j;
                int ltok = __ldg(letter_seq + b * S_ + s);
                int stok = __ldg(state_seq + b * S_ + s);
                float4 pl = __ldg((const float4*)(g_projL + ltok * G4 + c0 + (tc << 2)));
                float4 ps = __ldg((const float4*)(g_projS + stok * G4 + c0 + (tc << 2)));
                float xi = iv[ln] + pl.x + ps.x;
                float xf = fv[ln] + pl.y + ps.y;
                float xg = gv[ln] + pl.z + ps.z;
                float xo = ov[ln] + pl.w + ps.w;
                float I  = sigf(xi);
                float F  = sigf(xf);
                float O  = sigf(xo);
                float Gv = tanhfast(xg);
                float cc = F * cst[j] + I * Gv;
                cst[j] = cc;
                float hh = O * tanhfast(cc);
                hvals[j] = hh;
                int base = b * (S_ * H_) + s * H_ + myk;
                out[base] = hh;                       // hidden
                out[B_ * S_ * H_ + base] = cc;        // cell
            }
        }
        // publish h for next step (transposed layout, L2 via st.cg)
        float4 v0 = make_float4(hvals[0], hvals[1], hvals[2], hvals[3]);
        float4 v1 = make_float4(hvals[4], hvals[5], hvals[6], hvals[7]);
        __stcg((float4*)(hTn + myk * B_ + b0 + bbase), v0);
        __stcg((float4*)(hTn + myk * B_ + b0 + bbase + 4), v1);

        // ---- grid-wide barrier ----
        __syncthreads();
        if (t == 0) {
            __threadfence();
            atomicAdd(&g_bar, 1u);
            unsigned target = (unsigned)(s + 1) * grid;
            while (*((volatile unsigned*)&g_bar) < target) { }
        }
        __syncthreads();
    }
}

// ---------------------------------------------------------------------------
extern "C" void kernel_launch(void* const* d_in, const int* in_sizes, int n_in,
                              void* d_out, int out_size) {
    const int*   letter_seq = (const int*)d_in[0];
    const int*   state_seq  = (const int*)d_in[1];
    const float* letter_emb = (const float*)d_in[2];
    const float* state_emb  = (const float*)d_in[3];
    const float* W_ih       = (const float*)d_in[4];
    const float* W_hh       = (const float*)d_in[5];
    const float* b_ih       = (const float*)d_in[6];
    const float* b_hh       = (const float*)d_in[7];
    float* out = (float*)d_out;

    zero_kernel<<<(H_ * B_ + 255) / 256, 256>>>();
    proj_kernel<<<(34 * G4 + 255) / 256, 256>>>(letter_emb, state_emb, W_ih, b_ih, b_hh);
    wt_kernel<<<(H_ * G4) / 256, 256>>>(W_hh);
    lstm_kernel<<<128, 256>>>(letter_seq, state_seq, out);
}

// round 5
// speedup vs baseline: 2.9651x; 2.9540x over previous
#include <cuda_runtime.h>
#include <cuda_bf16.h>

#define B_  256
#define S_  256
#define E_  256
#define H_  1024
#define G4  4096

typedef unsigned int u32;
typedef unsigned long long u64;

// ---------------- device globals (static, no runtime alloc) ----------------
__device__ float g_projL[30 * G4];
__device__ float g_projS[4 * G4];
__device__ __nv_bfloat16 g_Whi[(size_t)G4 * H_];   // [c][kk], c = 4k+g reordered
__device__ __nv_bfloat16 g_Wlo[(size_t)G4 * H_];
__device__ __nv_bfloat16 g_hhi[2][B_ * H_];        // [parity][b*H+k]
__device__ __nv_bfloat16 g_hlo[2][B_ * H_];
__device__ u32 g_bar;

// ---------------- SMEM layout ----------------
#define SM_WHI     1024
#define SM_STAGE   132096          // 1024 + 16*8192
#define STAGE_SZ   40960
#define OFF_AHI    0
#define OFF_ALO    16384
#define OFF_BLO    32768
#define DPAD       272             // bytes per D-staging row (16B aligned, spreads banks)
#define DSLICE     34816           // 128 * 272
#define SMEM_TOTAL 214016          // 132096 + 2*40960 (D staging reuses stage bufs)

#define SWZ(x) ((x) ^ (((x) >> 3) & 0x70))

static __device__ __forceinline__ u32 smem_u32(const void* p) {
    u32 a;
    asm("{ .reg .u64 t; cvta.to.shared.u64 t, %1; cvt.u32.u64 %0, t; }"
        : "=r"(a) : "l"(p));
    return a;
}
#define CP16(dst, src) asm volatile( \
    "cp.async.cg.shared.global [%0], [%1], 16;" :: "r"(dst), "l"(src) : "memory")
#define CP_COMMIT() asm volatile("cp.async.commit_group;" ::: "memory")
#define CP_WAIT0()  asm volatile("cp.async.wait_group 0;" ::: "memory")
#define CP_WAIT1()  asm volatile("cp.async.wait_group 1;" ::: "memory")

#define LDSM_X4(r, addr) asm volatile( \
    "ldmatrix.sync.aligned.m8n8.x4.shared.b16 {%0,%1,%2,%3}, [%4];" \
    : "=r"((r)[0]), "=r"((r)[1]), "=r"((r)[2]), "=r"((r)[3]) : "r"(addr))

#define MMA16816(d, a, b) asm volatile( \
    "mma.sync.aligned.m16n8k16.row.col.f32.bf16.bf16.f32 " \
    "{%0,%1,%2,%3}, {%4,%5,%6,%7}, {%8,%9}, {%0,%1,%2,%3};" \
    : "+f"((d)[0]), "+f"((d)[1]), "+f"((d)[2]), "+f"((d)[3]) \
    : "r"((a)[0]), "r"((a)[1]), "r"((a)[2]), "r"((a)[3]), \
      "r"((b)[0]), "r"((b)[1]))

#define LDS128F(v, addr) asm volatile("ld.shared.v4.f32 {%0,%1,%2,%3}, [%4];" \
    : "=f"((v).x), "=f"((v).y), "=f"((v).z), "=f"((v).w) : "r"(addr))
#define STS64F(addr, x, y) asm volatile("st.shared.v2.f32 [%0], {%1,%2};" \
    :: "r"(addr), "f"(x), "f"(y) : "memory")

static __device__ __forceinline__ float sigf(float x) {
    return __fdividef(1.0f, 1.0f + __expf(-x));
}
static __device__ __forceinline__ float tanhfast(float x) {
    return __fdividef(2.0f, 1.0f + __expf(-2.0f * x)) - 1.0f;
}

// ---------------- prep kernels ----------------
__global__ void zero_kernel() {
    int idx = blockIdx.x * blockDim.x + threadIdx.x;
    if (idx < B_ * H_) {
        g_hhi[0][idx] = __float2bfloat16(0.0f);
        g_hlo[0][idx] = __float2bfloat16(0.0f);
    }
    if (idx == 0) g_bar = 0u;
}

__global__ void proj_kernel(const float* __restrict__ letter_emb,
                            const float* __restrict__ state_emb,
                            const float* __restrict__ W_ih,
                            const float* __restrict__ b_ih,
                            const float* __restrict__ b_hh) {
    int idx = blockIdx.x * blockDim.x + threadIdx.x;
    if (idx >= 34 * G4) return;
    int tbl = idx >> 12;
    int c   = idx & (G4 - 1);
    int k = c >> 2, g = c & 3;
    int r = g * H_ + k;
    if (tbl < 30) {
        const float* e = letter_emb + tbl * E_;
        const float* w = W_ih + (size_t)r * (2 * E_);
        float sum = __ldg(b_ih + r) + __ldg(b_hh + r);
        for (int i = 0; i < E_; i++) sum += __ldg(e + i) * __ldg(w + i);
        g_projL[tbl * G4 + c] = sum;
    } else {
        const float* e = state_emb + (tbl - 30) * E_;
        const float* w = W_ih + (size_t)r * (2 * E_) + E_;
        float sum = 0.0f;
        for (int i = 0; i < E_; i++) sum += __ldg(e + i) * __ldg(w + i);
        g_projS[(tbl - 30) * G4 + c] = sum;
    }
}

__global__ void wt_kernel(const float* __restrict__ W_hh) {
    int idx = blockIdx.x * blockDim.x + threadIdx.x;   // over G4*H_
    int c  = idx >> 10;
    int kk = idx & (H_ - 1);
    int k = c >> 2, g = c & 3;
    float w = __ldg(W_hh + (size_t)(g * H_ + k) * H_ + kk);
    __nv_bfloat16 hi = __float2bfloat16(w);
    g_Whi[idx] = hi;
    g_Wlo[idx] = __float2bfloat16(w - __bfloat162float(hi));
}

// ---------------- stage loader: one K-chunk of 64 ----------------
static __device__ __forceinline__ void load_stage(
    u32 sb, int buf, int ch,
    const __nv_bfloat16* __restrict__ hip,
    const __nv_bfloat16* __restrict__ lop,
    int b0, int c0) {
    int t = threadIdx.x;
    u32 st = sb + SM_STAGE + buf * STAGE_SZ;
    int kk0 = ch * 64;
#pragma unroll
    for (int i = 0; i < 4; i++) {                    // A hi: 128 rows x 8 segs
        int seg = t + 256 * i;
        int r = seg >> 3, q = seg & 7;
        CP16(st + OFF_AHI + SWZ(r * 128 + q * 16),
             hip + (size_t)(b0 + r) * H_ + kk0 + q * 8);
    }
#pragma unroll
    for (int i = 0; i < 4; i++) {                    // A lo
        int seg = t + 256 * i;
        int r = seg >> 3, q = seg & 7;
        CP16(st + OFF_ALO + SWZ(r * 128 + q * 16),
             lop + (size_t)(b0 + r) * H_ + kk0 + q * 8);
    }
#pragma unroll
    for (int i = 0; i < 2; i++) {                    // B lo: 64 rows x 8 segs
        int seg = t + 256 * i;
        int r = seg >> 3, q = seg & 7;
        CP16(st + OFF_BLO + SWZ(r * 128 + q * 16),
             g_Wlo + (size_t)(c0 + r) * H_ + kk0 + q * 8);
    }
}

// ---------------- persistent LSTM kernel (HMMA mma.sync) ----------------
__global__ void __launch_bounds__(256)
lstm_kernel(const int* __restrict__ letter_seq,
            const int* __restrict__ state_seq,
            float* __restrict__ out) {
    extern __shared__ char smem[];
    u32 sb = smem_u32(smem);
    const int t = threadIdx.x;
    const int lane = t & 31;
    const int wid = t >> 5;
    const int wm = wid & 1;            // M tile: rows 64*wm
    const int wn = (wid >> 1) & 1;     // N tile: cols 32*wn
    const int wk = wid >> 2;           // K slice: chunks [8*wk, 8*wk+8)
    const int bt = blockIdx.x >> 6;
    const int kt = blockIdx.x & 63;
    const int b0 = bt * 128;
    const int c0 = kt * 64;
    const int k0 = kt * 16;

    // ldmatrix per-lane address components
    const int arow = lane & 15;
    const int asel = (lane >> 4) * 16;
    const int brow = (lane & 7) + ((lane >> 4) & 1) * 8;
    const int bsel = ((lane >> 3) & 1) * 16;

    // preload resident Whi (16 chunks of [64 rows x 64 K] bf16, SW128)
#pragma unroll
    for (int i = 0; i < 32; i++) {
        int seg = t + 256 * i;                 // 8192 segs of 16B
        int ch = seg >> 9;
        int r  = (seg >> 3) & 63;
        int q  = seg & 7;
        CP16(sb + SM_WHI + ch * 8192 + SWZ(r * 128 + q * 16),
             g_Whi + (size_t)(c0 + r) * H_ + ch * 64 + q * 8);
    }
    CP_COMMIT();
    CP_WAIT0();
    __syncthreads();

    float cst[16];
#pragma unroll
    for (int j = 0; j < 16; j++) cst[j] = 0.0f;

    for (int s = 0; s < S_; ++s) {
        const __nv_bfloat16* hip = g_hhi[s & 1];
        const __nv_bfloat16* lop = g_hlo[s & 1];

        float D[4][4][4];
#pragma unroll
        for (int a = 0; a < 4; a++)
#pragma unroll
            for (int b = 0; b < 4; b++)
#pragma unroll
                for (int cq = 0; cq < 4; cq++) D[a][b][cq] = 0.0f;

        load_stage(sb, 0, 0, hip, lop, b0, c0);
        CP_COMMIT();

        for (int c = 0; c < 16; ++c) {
            int buf = c & 1;
            if (c < 15) {
                load_stage(sb, buf ^ 1, c + 1, hip, lop, b0, c0);
                CP_COMMIT();
                CP_WAIT1();
            } else {
                CP_WAIT0();
            }
            __syncthreads();

            if ((c >> 3) == wk) {
                u32 whib = sb + SM_WHI + c * 8192;
                u32 st = sb + SM_STAGE + buf * STAGE_SZ;
#pragma unroll
                for (int k2 = 0; k2 < 4; ++k2) {
                    int kb = k2 * 32;
                    u32 ahi[4][4], alo[4][4];
#pragma unroll
                    for (int mt = 0; mt < 4; ++mt) {
                        u32 off = SWZ((wm * 64 + mt * 16 + arow) * 128 + kb + asel);
                        LDSM_X4(ahi[mt], st + OFF_AHI + off);
                        LDSM_X4(alo[mt], st + OFF_ALO + off);
                    }
                    u32 bhi[4][2], blo[4][2];
#pragma unroll
                    for (int np = 0; np < 2; ++np) {
                        u32 off = SWZ((wn * 32 + np * 16 + brow) * 128 + kb + bsel);
                        u32 r4[4];
                        LDSM_X4(r4, whib + off);
                        bhi[2 * np][0] = r4[0]; bhi[2 * np][1] = r4[1];
                        bhi[2 * np + 1][0] = r4[2]; bhi[2 * np + 1][1] = r4[3];
                        LDSM_X4(r4, st + OFF_BLO + off);
                        blo[2 * np][0] = r4[0]; blo[2 * np][1] = r4[1];
                        blo[2 * np + 1][0] = r4[2]; blo[2 * np + 1][1] = r4[3];
                    }
#pragma unroll
                    for (int mt = 0; mt < 4; ++mt)
#pragma unroll
                        for (int nt = 0; nt < 4; ++nt) {
                            MMA16816(D[mt][nt], ahi[mt], bhi[nt]);
                            MMA16816(D[mt][nt], alo[mt], bhi[nt]);
                            MMA16816(D[mt][nt], ahi[mt], blo[nt]);
                        }
                }
            }
            __syncthreads();
        }

        // ---- write K-slice partials to SMEM ----
        {
            u32 dbase = sb + SM_STAGE + wk * DSLICE;
#pragma unroll
            for (int mt = 0; mt < 4; ++mt)
#pragma unroll
                for (int nt = 0; nt < 4; ++nt) {
                    int gr = wm * 64 + mt * 16 + (lane >> 2);
                    int gc = wn * 32 + nt * 8 + (lane & 3) * 2;
                    u32 a0 = dbase + gr * DPAD + gc * 4;
                    STS64F(a0, D[mt][nt][0], D[mt][nt][1]);
                    STS64F(a0 + 8 * DPAD, D[mt][nt][2], D[mt][nt][3]);
                }
        }
        __syncthreads();

        // ---- epilogue (threads 0..127, one batch row each) ----
        if (t < 128) {
            int b = b0 + t;
            int lt = __ldg(letter_seq + b * S_ + s);
            int st = __ldg(state_seq + b * S_ + s);
            const float4* pl = (const float4*)(g_projL + lt * G4 + c0);
            const float4* ps = (const float4*)(g_projS + st * G4 + c0);
            u32 dr0 = sb + SM_STAGE + t * DPAD;
            u32 dr1 = dr0 + DSLICE;

            float hv[16], cv[16];
            union { __nv_bfloat16 h[16]; int4 v[2]; } uh, ul;
#pragma unroll
            for (int j = 0; j < 16; j++) {
                float4 x0, x1;
                LDS128F(x0, dr0 + j * 16);
                LDS128F(x1, dr1 + j * 16);
                float4 a = __ldg(pl + j);
                float4 p = __ldg(ps + j);
                float xi = x0.x + x1.x + a.x + p.x;
                float xf = x0.y + x1.y + a.y + p.y;
                float xg = x0.z + x1.z + a.z + p.z;
                float xo = x0.w + x1.w + a.w + p.w;
                float I = sigf(xi), F = sigf(xf), O = sigf(xo), G = tanhfast(xg);
                float cc = F * cst[j] + I * G;
                cst[j] = cc;
                float hh = O * tanhfast(cc);
                hv[j] = hh; cv[j] = cc;
                __nv_bfloat16 hi16 = __float2bfloat16(hh);
                uh.h[j] = hi16;
                ul.h[j] = __float2bfloat16(hh - __bfloat162float(hi16));
            }
            size_t base = (size_t)b * (S_ * H_) + (size_t)s * H_ + k0;
            float4* po = (float4*)(out + base);
            float4* pc = (float4*)(out + (size_t)B_ * S_ * H_ + base);
#pragma unroll
            for (int q = 0; q < 4; q++) {
                po[q] = make_float4(hv[4*q], hv[4*q+1], hv[4*q+2], hv[4*q+3]);
                pc[q] = make_float4(cv[4*q], cv[4*q+1], cv[4*q+2], cv[4*q+3]);
            }
            int par = (s + 1) & 1;
            *(int4*)(&g_hhi[par][b * H_ + k0])     = uh.v[0];
            *(int4*)(&g_hhi[par][b * H_ + k0 + 8]) = uh.v[1];
            *(int4*)(&g_hlo[par][b * H_ + k0])     = ul.v[0];
            *(int4*)(&g_hlo[par][b * H_ + k0 + 8]) = ul.v[1];
        }

        // ---- grid-wide barrier ----
        __syncthreads();
        if (t == 0) {
            __threadfence();
            atomicAdd(&g_bar, 1u);
            u32 target = (u32)(s + 1) * (u32)gridDim.x;
            while (*((volatile u32*)&g_bar) < target) { }
        }
        __syncthreads();
    }
}

// ---------------------------------------------------------------------------
extern "C" void kernel_launch(void* const* d_in, const int* in_sizes, int n_in,
                              void* d_out, int out_size) {
    const int*   letter_seq = (const int*)d_in[0];
    const int*   state_seq  = (const int*)d_in[1];
    const float* letter_emb = (const float*)d_in[2];
    const float* state_emb  = (const float*)d_in[3];
    const float* W_ih       = (const float*)d_in[4];
    const float* W_hh       = (const float*)d_in[5];
    const float* b_ih       = (const float*)d_in[6];
    const float* b_hh       = (const float*)d_in[7];
    float* out = (float*)d_out;

    cudaFuncSetAttribute(lstm_kernel,
                         cudaFuncAttributeMaxDynamicSharedMemorySize, SMEM_TOTAL);

    zero_kernel<<<(B_ * H_ + 255) / 256, 256>>>();
    proj_kernel<<<(34 * G4 + 255) / 256, 256>>>(letter_emb, state_emb, W_ih, b_ih, b_hh);
    wt_kernel<<<((size_t)G4 * H_ + 255) / 256, 256>>>(W_hh);
    lstm_kernel<<<128, 256, SMEM_TOTAL>>>(letter_seq, state_seq, out);
}